// round 8
// baseline (speedup 1.0000x reference)
#include <cuda_runtime.h>

#define N_ROWS  8192
#define N_COLS  32000
#define NV4     (N_COLS / 4)      // 8000 float4 per row
#define K2      4915              // int(0.6 * int(1.0 * 8192))
#define THREADS 256

// Scratch (device globals — zero-initialized at module load; tail restores them)
__device__ unsigned int g_keys[N_ROWS];
__device__ unsigned int g_hist[2048];
__device__ unsigned int g_done;

__device__ __forceinline__ unsigned int key_of(float f) {
    unsigned int u = __float_as_uint(f);
    return u ^ ((u & 0x80000000u) ? 0xFFFFFFFFu : 0x80000000u);
}
__device__ __forceinline__ float val_of(unsigned int k) {
    return __uint_as_float((k & 0x80000000u) ? (k ^ 0x80000000u) : ~k);
}

// ---------------------------------------------------------------------------
// One fused kernel. Phase A (all 8192 blocks): per-row logsumexp loss, write
// transformed key, bin into global 2048-bin histogram (top 11 bits).
// Phase B (last block only): scan histogram, 3x7-bit radix refine over keys
// in L2, exact top-K2 mean, restore scratch state for next replay.
// ---------------------------------------------------------------------------
__global__ __launch_bounds__(THREADS, 6)
void fused_kernel(const float* __restrict__ x, const int* __restrict__ tgt,
                  float* __restrict__ out) {
    const int row = blockIdx.x;
    const int tid = threadIdx.x;
    const int wid = tid >> 5;
    const int lane = tid & 31;

    // ---------------- Phase A: row loss ----------------
    float xt = 0.f;
    if (tid == 0) xt = x[(size_t)row * N_COLS + tgt[row]];   // early gather

    const float4* __restrict__ rp =
        reinterpret_cast<const float4*>(x + (size_t)row * N_COLS);

    float s0 = 0.f, s1 = 0.f, s2 = 0.f, s3 = 0.f;
    int i = tid;
    for (; i + 3 * THREADS < NV4; i += 4 * THREADS) {
        const float4 a = __ldcs(rp + i);
        const float4 b = __ldcs(rp + i + THREADS);
        const float4 c = __ldcs(rp + i + 2 * THREADS);
        const float4 d = __ldcs(rp + i + 3 * THREADS);
        s0 += (__expf(a.x) + __expf(a.y)) + (__expf(a.z) + __expf(a.w));
        s1 += (__expf(b.x) + __expf(b.y)) + (__expf(b.z) + __expf(b.w));
        s2 += (__expf(c.x) + __expf(c.y)) + (__expf(c.z) + __expf(c.w));
        s3 += (__expf(d.x) + __expf(d.y)) + (__expf(d.z) + __expf(d.w));
    }
    for (; i < NV4; i += THREADS) {
        const float4 a = __ldcs(rp + i);
        s0 += (__expf(a.x) + __expf(a.y)) + (__expf(a.z) + __expf(a.w));
    }
    float s = (s0 + s1) + (s2 + s3);
    #pragma unroll
    for (int off = 16; off; off >>= 1)
        s += __shfl_xor_sync(0xffffffffu, s, off);

    __shared__ float sm_s[THREADS / 32];
    __shared__ unsigned int sh_last;
    if (lane == 0) sm_s[wid] = s;
    __syncthreads();

    if (tid == 0) {
        float t = 0.f;
        #pragma unroll
        for (int w = 0; w < THREADS / 32; w++) t += sm_s[w];
        const float loss = logf(t) - xt;
        const unsigned int key = key_of(loss);
        g_keys[row] = key;
        atomicAdd(&g_hist[key >> 21], 1u);
        __threadfence();
        const unsigned int old = atomicAdd(&g_done, 1u);
        sh_last = (old == (unsigned)(N_ROWS - 1)) ? 1u : 0u;
    }
    __syncthreads();
    if (!sh_last) return;

    // ---------------- Phase B: last block does selection ----------------
    __threadfence();   // acquire all other blocks' writes

    __shared__ unsigned int warp_tot[8];
    __shared__ unsigned int warp_off[8];
    __shared__ unsigned int sel[2];      // [0]=digit  [1]=new rem
    __shared__ unsigned int h2[128 * 4]; // 7-bit hist, 4 spread copies

    // Stage 1: block-wide suffix scan of the 2048-bin histogram (descending).
    {
        unsigned int hv[8], csum = 0u;
        const int base = 2047 - tid * 8;
        #pragma unroll
        for (int j = 0; j < 8; j++) { hv[j] = g_hist[base - j]; csum += hv[j]; }
        unsigned int pre = csum;
        #pragma unroll
        for (int off = 1; off < 32; off <<= 1) {
            const unsigned int v = __shfl_up_sync(0xffffffffu, pre, off);
            if (lane >= off) pre += v;
        }
        if (lane == 31) warp_tot[wid] = pre;
        __syncthreads();
        if (tid == 0) {
            unsigned int acc = 0u;
            #pragma unroll
            for (int w = 0; w < 8; w++) { warp_off[w] = acc; acc += warp_tot[w]; }
        }
        __syncthreads();
        unsigned int IS = warp_off[wid] + (pre - csum);
        #pragma unroll
        for (int j = 0; j < 8; j++) {
            const unsigned int lo = IS;
            IS += hv[j];
            if (IS >= K2 && lo < K2) { sel[0] = (unsigned)(base - j); sel[1] = K2 - lo; }
        }
        __syncthreads();
    }
    unsigned int prefix = sel[0] << 21;
    unsigned int rem = sel[1];

    // Stage 2: three 7-bit refinement passes over keys (L2-resident).
    for (int shift = 14; shift >= 0; shift -= 7) {
        h2[tid] = 0u; h2[tid + 256] = 0u;
        __syncthreads();
        const unsigned int mask = ~((1u << (shift + 7)) - 1u);
        const int spread = tid & 3;
        #pragma unroll 8
        for (int j = 0; j < 32; j++) {
            const unsigned int k = g_keys[j * 256 + tid];
            if ((k & mask) == prefix)
                atomicAdd(&h2[(((k >> shift) & 127u) << 2) + spread], 1u);
        }
        __syncthreads();
        if (tid < 32) {
            unsigned int hv2[4], cs = 0u;
            #pragma unroll
            for (int j = 0; j < 4; j++) {
                const int b = 127 - tid * 4 - j;
                const unsigned int t = h2[(b << 2)] + h2[(b << 2) + 1] +
                                       h2[(b << 2) + 2] + h2[(b << 2) + 3];
                hv2[j] = t; cs += t;
            }
            unsigned int pre2 = cs;
            #pragma unroll
            for (int off = 1; off < 32; off <<= 1) {
                const unsigned int v = __shfl_up_sync(0xffffffffu, pre2, off);
                if (tid >= off) pre2 += v;
            }
            unsigned int IS2 = pre2 - cs;
            #pragma unroll
            for (int j = 0; j < 4; j++) {
                const unsigned int lo = IS2;
                IS2 += hv2[j];
                if (IS2 >= rem && lo < rem) {
                    sel[0] = (unsigned)(127 - tid * 4 - j);
                    sel[1] = rem - lo;
                }
            }
        }
        __syncthreads();
        prefix |= sel[0] << (unsigned)shift;
        rem = sel[1];
        __syncthreads();   // protect sel before next pass rewrites it
    }
    const unsigned int T = prefix;       // exact key of the K2-th largest loss

    // Stage 3: mean of top-K2 (strictly-greater sum + ties at threshold).
    double acc = 0.0;
    unsigned int cnt = 0u;
    #pragma unroll 8
    for (int j = 0; j < 32; j++) {
        const unsigned int k = g_keys[j * 256 + tid];
        if (k > T) { acc += (double)val_of(k); cnt++; }
    }
    #pragma unroll
    for (int off = 16; off; off >>= 1) {
        acc += __shfl_down_sync(0xffffffffu, acc, off);
        cnt += __shfl_down_sync(0xffffffffu, cnt, off);
    }
    __shared__ double dacc[8];
    __shared__ unsigned int dcnt[8];
    if (lane == 0) { dacc[wid] = acc; dcnt[wid] = cnt; }
    __syncthreads();

    // Restore scratch state for the next graph replay (deterministic).
    #pragma unroll
    for (int j = 0; j < 8; j++) g_hist[tid * 8 + j] = 0u;

    if (tid == 0) {
        double tsum = 0.0;
        unsigned int tcnt = 0u;
        #pragma unroll
        for (int w = 0; w < 8; w++) { tsum += dacc[w]; tcnt += dcnt[w]; }
        tsum += (double)(K2 - tcnt) * (double)val_of(T);
        out[0] = (float)(tsum / (double)K2);
        g_done = 0u;
    }
}

// ---------------------------------------------------------------------------
extern "C" void kernel_launch(void* const* d_in, const int* in_sizes, int n_in,
                              void* d_out, int out_size) {
    const float* x   = (const float*)d_in[0];
    const int*   tgt = (const int*)d_in[1];
    float*       out = (float*)d_out;

    fused_kernel<<<N_ROWS, THREADS>>>(x, tgt, out);
}

// round 9
// speedup vs baseline: 1.0202x; 1.0202x over previous
#include <cuda_runtime.h>

#define N_ROWS  8192
#define N_COLS  32000
#define NV4     (N_COLS / 4)      // 8000 float4 per row
#define K2      4915              // int(0.6 * int(1.0 * 8192))
#define THREADS 256

// Scratch (device globals — zero-initialized at module load; tail restores them)
__device__ unsigned int g_keys[N_ROWS];
__device__ unsigned int g_hist[2048];
__device__ unsigned int g_done;

__device__ __forceinline__ unsigned int key_of(float f) {
    unsigned int u = __float_as_uint(f);
    return u ^ ((u & 0x80000000u) ? 0xFFFFFFFFu : 0x80000000u);
}
__device__ __forceinline__ float val_of(unsigned int k) {
    return __uint_as_float((k & 0x80000000u) ? (k ^ 0x80000000u) : ~k);
}

// ---------------------------------------------------------------------------
// One fused kernel, forced to 32 regs / full occupancy via launch bounds.
// Phase A (all 8192 blocks): per-row logsumexp loss -> key + global histogram.
// Phase B (last finishing block): histogram scan + 3x7-bit radix refine over
// keys in L2, exact top-K2 mean, restore scratch for next graph replay.
// ---------------------------------------------------------------------------
__global__ __launch_bounds__(THREADS, 8)
void fused_kernel(const float* __restrict__ x, const int* __restrict__ tgt,
                  float* __restrict__ out) {
    const int row = blockIdx.x;
    const int tid = threadIdx.x;
    const int wid = tid >> 5;
    const int lane = tid & 31;

    // ---------------- Phase A: row loss ----------------
    const float4* __restrict__ rp =
        reinterpret_cast<const float4*>(x + (size_t)row * N_COLS);

    float s0 = 0.f, s1 = 0.f, s2 = 0.f, s3 = 0.f;
    // 8000 = 31 * 256 + 32: do 8 strided steps of 4, last quad guarded.
    #pragma unroll 1
    for (int i = tid; i < NV4; i += 4 * THREADS) {
        const float4 a = __ldcs(rp + i);
        s0 += (__expf(a.x) + __expf(a.y)) + (__expf(a.z) + __expf(a.w));
        if (i + THREADS < NV4) {
            const float4 b = __ldcs(rp + i + THREADS);
            s1 += (__expf(b.x) + __expf(b.y)) + (__expf(b.z) + __expf(b.w));
        }
        if (i + 2 * THREADS < NV4) {
            const float4 c = __ldcs(rp + i + 2 * THREADS);
            s2 += (__expf(c.x) + __expf(c.y)) + (__expf(c.z) + __expf(c.w));
        }
        if (i + 3 * THREADS < NV4) {
            const float4 d = __ldcs(rp + i + 3 * THREADS);
            s3 += (__expf(d.x) + __expf(d.y)) + (__expf(d.z) + __expf(d.w));
        }
    }
    float s = (s0 + s1) + (s2 + s3);
    #pragma unroll
    for (int off = 16; off; off >>= 1)
        s += __shfl_xor_sync(0xffffffffu, s, off);

    __shared__ float sm_s[THREADS / 32];
    __shared__ unsigned int sh_last;
    if (lane == 0) sm_s[wid] = s;
    __syncthreads();

    if (tid == 0) {
        float t = 0.f;
        #pragma unroll
        for (int w = 0; w < THREADS / 32; w++) t += sm_s[w];
        const float loss = logf(t) - x[(size_t)row * N_COLS + tgt[row]];
        const unsigned int key = key_of(loss);
        g_keys[row] = key;
        atomicAdd(&g_hist[key >> 21], 1u);
        __threadfence();
        const unsigned int old = atomicAdd(&g_done, 1u);
        sh_last = (old == (unsigned)(N_ROWS - 1)) ? 1u : 0u;
    }
    __syncthreads();
    if (!sh_last) return;

    // ---------------- Phase B: last block does selection ----------------
    __threadfence();   // acquire all other blocks' writes

    __shared__ unsigned int warp_tot[8];
    __shared__ unsigned int warp_off[8];
    __shared__ unsigned int sel[2];      // [0]=digit  [1]=new rem
    __shared__ unsigned int h2[128 * 4]; // 7-bit hist, 4 spread copies

    // Stage 1: block-wide suffix scan of the 2048-bin histogram (descending).
    {
        unsigned int hv[8], csum = 0u;
        const int base = 2047 - tid * 8;
        #pragma unroll
        for (int j = 0; j < 8; j++) { hv[j] = g_hist[base - j]; csum += hv[j]; }
        unsigned int pre = csum;
        #pragma unroll
        for (int off = 1; off < 32; off <<= 1) {
            const unsigned int v = __shfl_up_sync(0xffffffffu, pre, off);
            if (lane >= off) pre += v;
        }
        if (lane == 31) warp_tot[wid] = pre;
        __syncthreads();
        if (tid == 0) {
            unsigned int acc = 0u;
            #pragma unroll
            for (int w = 0; w < 8; w++) { warp_off[w] = acc; acc += warp_tot[w]; }
        }
        __syncthreads();
        unsigned int IS = warp_off[wid] + (pre - csum);
        #pragma unroll
        for (int j = 0; j < 8; j++) {
            const unsigned int lo = IS;
            IS += hv[j];
            if (IS >= K2 && lo < K2) { sel[0] = (unsigned)(base - j); sel[1] = K2 - lo; }
        }
        __syncthreads();
    }
    unsigned int prefix = sel[0] << 21;
    unsigned int rem = sel[1];

    // Stage 2: three 7-bit refinement passes over keys (L2-resident).
    for (int shift = 14; shift >= 0; shift -= 7) {
        h2[tid] = 0u; h2[tid + 256] = 0u;
        __syncthreads();
        const unsigned int mask = ~((1u << (shift + 7)) - 1u);
        const int spread = tid & 3;
        #pragma unroll 8
        for (int j = 0; j < 32; j++) {
            const unsigned int k = g_keys[j * 256 + tid];
            if ((k & mask) == prefix)
                atomicAdd(&h2[(((k >> shift) & 127u) << 2) + spread], 1u);
        }
        __syncthreads();
        if (tid < 32) {
            unsigned int hv2[4], cs = 0u;
            #pragma unroll
            for (int j = 0; j < 4; j++) {
                const int b = 127 - tid * 4 - j;
                const unsigned int t = h2[(b << 2)] + h2[(b << 2) + 1] +
                                       h2[(b << 2) + 2] + h2[(b << 2) + 3];
                hv2[j] = t; cs += t;
            }
            unsigned int pre2 = cs;
            #pragma unroll
            for (int off = 1; off < 32; off <<= 1) {
                const unsigned int v = __shfl_up_sync(0xffffffffu, pre2, off);
                if (tid >= off) pre2 += v;
            }
            unsigned int IS2 = pre2 - cs;
            #pragma unroll
            for (int j = 0; j < 4; j++) {
                const unsigned int lo = IS2;
                IS2 += hv2[j];
                if (IS2 >= rem && lo < rem) {
                    sel[0] = (unsigned)(127 - tid * 4 - j);
                    sel[1] = rem - lo;
                }
            }
        }
        __syncthreads();
        prefix |= sel[0] << (unsigned)shift;
        rem = sel[1];
        __syncthreads();   // protect sel before next pass rewrites it
    }
    const unsigned int T = prefix;       // exact key of the K2-th largest loss

    // Stage 3: mean of top-K2 (strictly-greater sum + ties at threshold).
    double acc = 0.0;
    unsigned int cnt = 0u;
    #pragma unroll 8
    for (int j = 0; j < 32; j++) {
        const unsigned int k = g_keys[j * 256 + tid];
        if (k > T) { acc += (double)val_of(k); cnt++; }
    }
    #pragma unroll
    for (int off = 16; off; off >>= 1) {
        acc += __shfl_down_sync(0xffffffffu, acc, off);
        cnt += __shfl_down_sync(0xffffffffu, cnt, off);
    }
    __shared__ double dacc[8];
    __shared__ unsigned int dcnt[8];
    if (lane == 0) { dacc[wid] = acc; dcnt[wid] = cnt; }
    __syncthreads();

    // Restore scratch state for the next graph replay (deterministic).
    #pragma unroll
    for (int j = 0; j < 8; j++) g_hist[tid * 8 + j] = 0u;

    if (tid == 0) {
        double tsum = 0.0;
        unsigned int tcnt = 0u;
        #pragma unroll
        for (int w = 0; w < 8; w++) { tsum += dacc[w]; tcnt += dcnt[w]; }
        tsum += (double)(K2 - tcnt) * (double)val_of(T);
        out[0] = (float)(tsum / (double)K2);
        g_done = 0u;
    }
}

// ---------------------------------------------------------------------------
extern "C" void kernel_launch(void* const* d_in, const int* in_sizes, int n_in,
                              void* d_out, int out_size) {
    const float* x   = (const float*)d_in[0];
    const int*   tgt = (const int*)d_in[1];
    float*       out = (float*)d_out;

    fused_kernel<<<N_ROWS, THREADS>>>(x, tgt, out);
}

// round 13
// speedup vs baseline: 1.0362x; 1.0156x over previous
#include <cuda_runtime.h>

#define N_ROWS  8192
#define N_COLS  32000
#define NV4     (N_COLS / 4)      // 8000 float4 per row
#define K2      4915              // int(0.6 * int(1.0 * 8192))
#define THREADS 256

// Scratch (device globals — zero-init at load; select kernel restores g_hist)
__device__ unsigned int g_keys[N_ROWS];
__device__ unsigned int g_hist[2048];

__device__ __forceinline__ unsigned int key_of(float f) {
    unsigned int u = __float_as_uint(f);
    return u ^ ((u & 0x80000000u) ? 0xFFFFFFFFu : 0x80000000u);
}
__device__ __forceinline__ float val_of(unsigned int k) {
    return __uint_as_float((k & 0x80000000u) ? (k ^ 0x80000000u) : ~k);
}

// ---------------------------------------------------------------------------
// Kernel 1: one block per row, single-pass logsumexp loss. Identical mainloop
// to the 90.6%-of-HBM version; tail additionally writes the transformed key
// and one histogram atomic (distributes the contended radix pass for free).
// ---------------------------------------------------------------------------
__global__ __launch_bounds__(THREADS) void loss_kernel(const float* __restrict__ x,
                                                       const int* __restrict__ tgt) {
    const int row = blockIdx.x;
    const float4* __restrict__ rp =
        reinterpret_cast<const float4*>(x + (size_t)row * N_COLS);

    float s0 = 0.f, s1 = 0.f, s2 = 0.f, s3 = 0.f;

    int i = threadIdx.x;
    for (; i + 3 * THREADS < NV4; i += 4 * THREADS) {
        const float4 a = __ldcs(rp + i);
        const float4 b = __ldcs(rp + i + THREADS);
        const float4 c = __ldcs(rp + i + 2 * THREADS);
        const float4 d = __ldcs(rp + i + 3 * THREADS);
        s0 += (__expf(a.x) + __expf(a.y)) + (__expf(a.z) + __expf(a.w));
        s1 += (__expf(b.x) + __expf(b.y)) + (__expf(b.z) + __expf(b.w));
        s2 += (__expf(c.x) + __expf(c.y)) + (__expf(c.z) + __expf(c.w));
        s3 += (__expf(d.x) + __expf(d.y)) + (__expf(d.z) + __expf(d.w));
    }
    for (; i < NV4; i += THREADS) {
        const float4 a = __ldcs(rp + i);
        s0 += (__expf(a.x) + __expf(a.y)) + (__expf(a.z) + __expf(a.w));
    }

    float s = (s0 + s1) + (s2 + s3);
    #pragma unroll
    for (int off = 16; off; off >>= 1)
        s += __shfl_xor_sync(0xffffffffu, s, off);

    __shared__ float sm_s[THREADS / 32];
    const int warp = threadIdx.x >> 5;
    const int lane = threadIdx.x & 31;
    if (lane == 0) sm_s[warp] = s;
    __syncthreads();

    if (threadIdx.x == 0) {
        float t = 0.f;
        #pragma unroll
        for (int w = 0; w < THREADS / 32; w++) t += sm_s[w];
        const float loss = logf(t) - x[(size_t)row * N_COLS + tgt[row]];
        const unsigned int key = key_of(loss);
        g_keys[row] = key;
        atomicAdd(&g_hist[key >> 21], 1u);   // top-11-bit bucket, spread over grid
    }
}

// ---------------------------------------------------------------------------
// Kernel 2: single block, 256 threads. Starts from the prebuilt 2048-bin
// histogram (11 bits already resolved), re-zeroes it for replay determinism,
// then 3x7-bit refinement passes over keys in L2, exact top-K2 mean.
// ---------------------------------------------------------------------------
__global__ __launch_bounds__(256) void select_mean_kernel(float* __restrict__ out) {
    const int tid = threadIdx.x;
    const int wid = tid >> 5;
    const int lane = tid & 31;

    __shared__ unsigned int warp_tot[8];
    __shared__ unsigned int warp_off[8];
    __shared__ unsigned int sel[2];      // [0]=digit  [1]=new rem
    __shared__ unsigned int h2[128 * 4]; // 7-bit hist, 4 spread copies

    // Stage 1: block-wide suffix scan of the 2048-bin histogram (descending),
    // zeroing bins as we read them (restores state for the next graph replay).
    {
        unsigned int hv[8], csum = 0u;
        const int base = 2047 - tid * 8;
        #pragma unroll
        for (int j = 0; j < 8; j++) {
            hv[j] = g_hist[base - j];
            g_hist[base - j] = 0u;
            csum += hv[j];
        }
        unsigned int pre = csum;
        #pragma unroll
        for (int off = 1; off < 32; off <<= 1) {
            const unsigned int v = __shfl_up_sync(0xffffffffu, pre, off);
            if (lane >= off) pre += v;
        }
        if (lane == 31) warp_tot[wid] = pre;
        __syncthreads();
        if (tid == 0) {
            unsigned int acc = 0u;
            #pragma unroll
            for (int w = 0; w < 8; w++) { warp_off[w] = acc; acc += warp_tot[w]; }
        }
        __syncthreads();
        unsigned int IS = warp_off[wid] + (pre - csum);
        #pragma unroll
        for (int j = 0; j < 8; j++) {
            const unsigned int lo = IS;
            IS += hv[j];
            if (IS >= K2 && lo < K2) { sel[0] = (unsigned)(base - j); sel[1] = K2 - lo; }
        }
        __syncthreads();
    }
    unsigned int prefix = sel[0] << 21;
    unsigned int rem = sel[1];

    // Stage 2: three 7-bit refinement passes over keys (L2-resident, 32 KB).
    for (int shift = 14; shift >= 0; shift -= 7) {
        h2[tid] = 0u; h2[tid + 256] = 0u;
        __syncthreads();
        const unsigned int mask = ~((1u << (shift + 7)) - 1u);
        const int spread = tid & 3;
        #pragma unroll 8
        for (int j = 0; j < 32; j++) {
            const unsigned int k = g_keys[j * 256 + tid];
            if ((k & mask) == prefix)
                atomicAdd(&h2[(((k >> shift) & 127u) << 2) + spread], 1u);
        }
        __syncthreads();
        if (tid < 32) {
            unsigned int hv2[4], cs = 0u;
            #pragma unroll
            for (int j = 0; j < 4; j++) {
                const int b = 127 - tid * 4 - j;
                const unsigned int t = h2[(b << 2)] + h2[(b << 2) + 1] +
                                       h2[(b << 2) + 2] + h2[(b << 2) + 3];
                hv2[j] = t; cs += t;
            }
            unsigned int pre2 = cs;
            #pragma unroll
            for (int off = 1; off < 32; off <<= 1) {
                const unsigned int v = __shfl_up_sync(0xffffffffu, pre2, off);
                if (tid >= off) pre2 += v;
            }
            unsigned int IS2 = pre2 - cs;
            #pragma unroll
            for (int j = 0; j < 4; j++) {
                const unsigned int lo = IS2;
                IS2 += hv2[j];
                if (IS2 >= rem && lo < rem) {
                    sel[0] = (unsigned)(127 - tid * 4 - j);
                    sel[1] = rem - lo;
                }
            }
        }
        __syncthreads();
        prefix |= sel[0] << (unsigned)shift;
        rem = sel[1];
        __syncthreads();   // protect sel before next pass rewrites it
    }
    const unsigned int T = prefix;       // exact key of the K2-th largest loss

    // Stage 3: mean of top-K2 (strictly-greater sum + ties at threshold).
    double acc = 0.0;
    unsigned int cnt = 0u;
    #pragma unroll 8
    for (int j = 0; j < 32; j++) {
        const unsigned int k = g_keys[j * 256 + tid];
        if (k > T) { acc += (double)val_of(k); cnt++; }
    }
    #pragma unroll
    for (int off = 16; off; off >>= 1) {
        acc += __shfl_down_sync(0xffffffffu, acc, off);
        cnt += __shfl_down_sync(0xffffffffu, cnt, off);
    }
    __shared__ double dacc[8];
    __shared__ unsigned int dcnt[8];
    if (lane == 0) { dacc[wid] = acc; dcnt[wid] = cnt; }
    __syncthreads();

    if (tid == 0) {
        double tsum = 0.0;
        unsigned int tcnt = 0u;
        #pragma unroll
        for (int w = 0; w < 8; w++) { tsum += dacc[w]; tcnt += dcnt[w]; }
        tsum += (double)(K2 - tcnt) * (double)val_of(T);
        out[0] = (float)(tsum / (double)K2);
    }
}

// ---------------------------------------------------------------------------
extern "C" void kernel_launch(void* const* d_in, const int* in_sizes, int n_in,
                              void* d_out, int out_size) {
    const float* x   = (const float*)d_in[0];
    const int*   tgt = (const int*)d_in[1];
    float*       out = (float*)d_out;

    loss_kernel<<<N_ROWS, THREADS>>>(x, tgt);
    select_mean_kernel<<<1, 256>>>(out);
}